// round 17
// baseline (speedup 1.0000x reference)
#include <cuda_runtime.h>
#include <stdint.h>

// Problem dims (fixed by the reference)
#define BATCH 1024
#define M     2048
#define R     8192
#define ROWB  (BATCH * 4)   // 4096 bytes per [*, B] row  (matches <<12 packing)

#define MAX_E 32   // max nnz per reaction column of E (mean ~4.1)
#define MAX_S 64   // max nnz per metabolite row of S (mean ~16.4)

#define TRANS_BLOCKS ((M / 32) * (BATCH / 32))          // 2048
#define SPARS_BLOCKS ((M * R / 4) / 256)                // 16384

#define GI 32    // metabolites per gather CTA
#define GB 256   // batch per gather CTA

// Scratch (device globals — no allocation allowed; zero-initialized at load)
__device__ int e_cnt[R];
__device__ int s_cnt[M];
// Precomputed byte-offset entries:
//  E entry: (i << 12) | (exp-1)   -> byte offset into ct_buf, exp bit in bit0
//  S entry: (j << 12) | code      -> byte offset into v_buf, code: -2->0,-1->1,1->2,2->3
__device__ unsigned e_list[R * MAX_E];
__device__ unsigned s_list[M * MAX_S];
__device__ float ct_buf[M * BATCH];           // conc transposed  [M][B]   (8 MB)
__device__ float v_buf[(size_t)R * BATCH];    // rates            [R][B]   (32 MB)

// ---------------------------------------------------------------------------
// prep: blocks [0, TRANS_BLOCKS) transpose conc [B][M] -> ct [M][B];
//       blocks [TRANS_BLOCKS, ...) scan dense E,S and build offset lists.
// (Counters are reset by reset_kernel at the END of the previous call.)
__global__ __launch_bounds__(256) void prep_kernel(const float* __restrict__ conc,
                                                   const int* __restrict__ E,
                                                   const int* __restrict__ S) {
    __shared__ float tile[32][33];
    const int bid = blockIdx.x;

    if (bid < TRANS_BLOCKS) {
        // ---- transpose conc (rows=B, cols=M) into ct_buf [M][B] ----
        const int c0 = (bid & 63) * 32;          // over M (2048/32 = 64 blocks)
        const int r0 = (bid >> 6) * 32;          // over B
        const int lx = threadIdx.x & 31;
        const int ly = threadIdx.x >> 5;         // 0..7
        #pragma unroll
        for (int r = 0; r < 32; r += 8)
            tile[r + ly][lx] = conc[(size_t)(r0 + r + ly) * M + c0 + lx];
        __syncthreads();
        #pragma unroll
        for (int r = 0; r < 32; r += 8)
            ct_buf[(size_t)(c0 + r + ly) * BATCH + r0 + lx] = tile[lx][r + ly];
        return;
    }

    // ---- sparsify: one int4 of E and S per thread ----
    const int t = (bid - TRANS_BLOCKS) * 256 + threadIdx.x;
    const int base = t * 4;
    const int i  = base >> 13;        // / R
    const int j0 = base & (R - 1);    // % R

    int4 ev = __ldg(reinterpret_cast<const int4*>(E) + t);
    int4 sv = __ldg(reinterpret_cast<const int4*>(S) + t);

    int evs[4] = {ev.x, ev.y, ev.z, ev.w};
    int svs[4] = {sv.x, sv.y, sv.z, sv.w};

    #pragma unroll
    for (int u = 0; u < 4; ++u) {
        int j = j0 + u;
        int e = evs[u];
        if (e != 0) {
            int p = atomicAdd(&e_cnt[j], 1);
            if (p < MAX_E)
                e_list[j * MAX_E + p] = ((unsigned)i << 12) | (unsigned)(e - 1);
        }
        int s = svs[u];
        if (s != 0) {
            int code = (s < 0) ? (s + 2) : (s + 1);   // -2->0, -1->1, 1->2, 2->3
            int p = atomicAdd(&s_cnt[i], 1);
            if (p < MAX_S)
                s_list[i * MAX_S + p] = ((unsigned)j << 12) | (unsigned)code;
        }
    }
}

// ---------------------------------------------------------------------------
// Rates: CTA j computes v[j][b] = k_j * prod_i ct[i][b]^{E_ij}, 128 threads,
// two float4 chunks per thread (bytes tb and tb+2048) for 2x ILP.
__device__ __forceinline__ void rate_apply(float4& p0, float4& p1, unsigned pk,
                                           const char* ctb, int tb0) {
    const char* src = ctb + (pk & 0xFFFFF000u);
    float4 c0 = *reinterpret_cast<const float4*>(src + tb0);
    float4 c1 = *reinterpret_cast<const float4*>(src + tb0 + 2048);
    if (pk & 1) {
        c0.x *= c0.x; c0.y *= c0.y; c0.z *= c0.z; c0.w *= c0.w;
        c1.x *= c1.x; c1.y *= c1.y; c1.z *= c1.z; c1.w *= c1.w;
    }
    p0.x *= c0.x; p0.y *= c0.y; p0.z *= c0.z; p0.w *= c0.w;
    p1.x *= c1.x; p1.y *= c1.y; p1.z *= c1.z; p1.w *= c1.w;
}

__global__ __launch_bounds__(128) void rate_kernel(const float* __restrict__ krate) {
    const int j   = blockIdx.x;
    const int tb0 = threadIdx.x * 16;
    const char* ctb = reinterpret_cast<const char*>(ct_buf);
    int cnt = e_cnt[j];
    cnt = cnt < MAX_E ? cnt : MAX_E;
    const float kj = __ldg(&krate[j]);
    float4 p0 = make_float4(kj, kj, kj, kj);
    float4 p1 = p0;

    const unsigned* el = e_list + j * MAX_E;
    const uint4 w0 = *reinterpret_cast<const uint4*>(el);      // entries 0-3 (broadcast)
    const uint4 w1 = *reinterpret_cast<const uint4*>(el + 4);  // entries 4-7
    const unsigned e8[8] = {w0.x, w0.y, w0.z, w0.w, w1.x, w1.y, w1.z, w1.w};
    #pragma unroll
    for (int t = 0; t < 8; ++t)
        if (t < cnt) rate_apply(p0, p1, e8[t], ctb, tb0);
    for (int t = 8; t < cnt; ++t)                     // rare tail (P ~ 3%)
        rate_apply(p0, p1, el[t], ctb, tb0);

    char* dst = reinterpret_cast<char*>(v_buf) + (size_t)j * ROWB;
    *reinterpret_cast<float4*>(dst + tb0)        = p0;
    *reinterpret_cast<float4*>(dst + tb0 + 2048) = p1;
}

// ---------------------------------------------------------------------------
// Gather + output transpose fused: CTA (bx, by) covers batch block
// [bx*GB, +GB) x metabolites [by*GI, +GI). Accumulates in batch-major
// registers (coalesced v reads), stages the tile in smem, writes out[b][i]
// coalesced (128 B per warp).
__global__ __launch_bounds__(256) void gather_kernel(float* __restrict__ out) {
    __shared__ float tile[GB][GI + 1];   // [b][i], pad -> conflict-free transposed read
    const int b0 = blockIdx.x * GB;
    const int i0 = blockIdx.y * GI;
    const int w  = threadIdx.x >> 5;     // warp 0..7
    const int l  = threadIdx.x & 31;
    const char* vb = reinterpret_cast<const char*>(v_buf);
    const int boff = b0 * 4 + l * 16;    // lane's chunk0 byte offset within a v row

    #pragma unroll
    for (int s = 0; s < GI; s += 8) {
        const int iw = s + w;            // local metabolite index
        const int i  = i0 + iw;
        int cnt = s_cnt[i];
        cnt = cnt < MAX_S ? cnt : MAX_S;
        const unsigned* sl = s_list + i * MAX_S;

        float4 a0 = make_float4(0.f, 0.f, 0.f, 0.f);
        float4 a1 = a0;
        for (int t = 0; t < cnt; ++t) {
            const unsigned pk = __ldg(&sl[t]);
            const int code = pk & 3;
            const float coeff = (float)(code - (code < 2 ? 2 : 1));  // {-2,-1,1,2}
            const char* src = vb + (pk & 0xFFFFF000u);
            const float4 v0 = *reinterpret_cast<const float4*>(src + boff);
            const float4 v1 = *reinterpret_cast<const float4*>(src + boff + 512);
            a0.x = fmaf(coeff, v0.x, a0.x); a0.y = fmaf(coeff, v0.y, a0.y);
            a0.z = fmaf(coeff, v0.z, a0.z); a0.w = fmaf(coeff, v0.w, a0.w);
            a1.x = fmaf(coeff, v1.x, a1.x); a1.y = fmaf(coeff, v1.y, a1.y);
            a1.z = fmaf(coeff, v1.z, a1.z); a1.w = fmaf(coeff, v1.w, a1.w);
        }
        const int bl0 = l * 4;           // chunk0 local batch index
        tile[bl0 + 0][iw] = a0.x; tile[bl0 + 1][iw] = a0.y;
        tile[bl0 + 2][iw] = a0.z; tile[bl0 + 3][iw] = a0.w;
        tile[bl0 + 128 + 0][iw] = a1.x; tile[bl0 + 128 + 1][iw] = a1.y;
        tile[bl0 + 128 + 2][iw] = a1.z; tile[bl0 + 128 + 3][iw] = a1.w;
    }
    __syncthreads();

    // Write out[b][i]: warp lanes cover 32 contiguous i -> 128 B per warp.
    #pragma unroll
    for (int m = 0; m < (GI * GB) / 256; ++m) {
        const int idx = threadIdx.x + m * 256;
        const int i = idx & (GI - 1);
        const int b = idx >> 5;
        out[(size_t)(b0 + b) * M + i0 + i] = tile[b][i];
    }
}

// ---------------------------------------------------------------------------
// End-of-call counter reset (so the NEXT call's sparsify starts clean;
// device globals are zero-initialized for the very first call).
__global__ void reset_kernel() {
    int t = blockIdx.x * blockDim.x + threadIdx.x;
    if (t < R) e_cnt[t] = 0;
    if (t < M) s_cnt[t] = 0;
}

// ---------------------------------------------------------------------------
extern "C" void kernel_launch(void* const* d_in, const int* in_sizes, int n_in,
                              void* d_out, int out_size) {
    const float* conc = (const float*)d_in[0];   // [B, M]
    const int*   E    = (const int*)d_in[1];     // [M, R]
    const int*   S    = (const int*)d_in[2];     // [M, R]
    const float* k    = (const float*)d_in[3];   // [R]
    float*       out  = (float*)d_out;           // [B, M]

    // 1) transpose conc -> ct  (overlapped with)  sparse-list build from E,S
    prep_kernel<<<TRANS_BLOCKS + SPARS_BLOCKS, 256>>>(conc, E, S);
    // 2) v[j][b] = k_j * prod c^e  — coalesced over batch
    rate_kernel<<<R, 128>>>(k);
    // 3) out[b][i] = sum_j v[j][b] * S_ij  (fused gather + transpose)
    {
        dim3 grid(BATCH / GB, M / GI);
        gather_kernel<<<grid, 256>>>(out);
    }
    // 4) reset counters for the next call
    reset_kernel<<<(R + 255) / 256, 256>>>();
}